// round 16
// baseline (speedup 1.0000x reference)
#include <cuda_runtime.h>
#include <cuda.h>
#include <math.h>

#define Nn 128
#define C  2048
#define L  512
#define TT 512

// -------- scratch (device globals; no allocations allowed) --------
__device__ float g_theta[Nn*L];
__device__ float g_v[Nn*C];
__device__ float g_lat[Nn*L];
__device__ float g_part[16*Nn*L > 4*Nn*C ? 16*Nn*L : 4*Nn*C];  // split-K partials

// ---- f32x2 helpers ----
__device__ __forceinline__ unsigned long long pack2(float a, float b) {
    unsigned long long r;
    asm("mov.b64 %0, {%1, %2};" : "=l"(r) : "r"(__float_as_uint(a)), "r"(__float_as_uint(b)));
    return r;
}
__device__ __forceinline__ void unpack2(unsigned long long d, float& a, float& b) {
    unsigned x, y;
    asm("mov.b64 {%0, %1}, %2;" : "=r"(x), "=r"(y) : "l"(d));
    a = __uint_as_float(x); b = __uint_as_float(y);
}
__device__ __forceinline__ void ffma2(unsigned long long& d, unsigned long long a, unsigned long long b) {
    asm("fma.rn.f32x2 %0, %1, %2, %0;" : "+l"(d) : "l"(a), "l"(b));
}
__device__ __forceinline__ void fadd2(unsigned long long& d, unsigned long long a) {
    asm("add.rn.f32x2 %0, %0, %1;" : "+l"(d) : "l"(a));
}
__device__ __forceinline__ unsigned smem_u32(const void* p) {
    return (unsigned)__cvta_generic_to_shared(p);
}

// ============ projection: packed-f32x2, CTA = 128 oc x 64 n, split-K ============
// Register-prefetch double buffering: block kb+1's LDGs are issued before
// computing block kb, hiding weight-DRAM latency at each barrier.
template<bool WT>
__global__ __launch_bounds__(256) void proj2_kernel(
    const float* __restrict__ act, const float* __restrict__ w,
    float* __restrict__ part, int K, int O, int kchunk)
{
    __shared__ float ws[32*132];
    __shared__ float th[64*36];
    const int tid = threadIdx.x;
    const int lane = tid & 31;
    const int wid = tid >> 5;
    const int ocbase = blockIdx.x * 128;
    const int nbase  = blockIdx.y * 64;
    const int sidx   = blockIdx.z;
    const int k0 = sidx * kchunk;

    unsigned long long acc[2][8];
#pragma unroll
    for (int p = 0; p < 2; p++)
#pragma unroll
        for (int j = 0; j < 8; j++) acc[p][j] = 0ull;

    float4 sa[2], sw[4];

    // prologue: load block k0 into regs
#pragma unroll
    for (int j = 0; j < 2; j++) {
        int f = tid + 256*j;
        int n = f >> 3;
        int kq = (f & 7) << 2;
        sa[j] = *(const float4*)(act + (size_t)(nbase+n)*K + k0 + kq);
    }
#pragma unroll
    for (int j = 0; j < 4; j++) {
        int f = tid + 256*j;
        if (WT) {
            int kk = f >> 5;
            int oq = (f & 31) << 2;
            sw[j] = *(const float4*)(w + (size_t)(k0+kk)*O + ocbase + oq);
        } else {
            int o = f >> 3;
            int kq = (f & 7) << 2;
            sw[j] = *(const float4*)(w + (size_t)(ocbase+o)*K + k0 + kq);
        }
    }

    for (int kb = k0; kb < k0 + kchunk; kb += 32) {
        // store staged regs to smem
#pragma unroll
        for (int j = 0; j < 2; j++) {
            int f = tid + 256*j;
            int n = f >> 3;
            int kq = (f & 7) << 2;
            *(float4*)(th + n*36 + kq) = sa[j];
        }
#pragma unroll
        for (int j = 0; j < 4; j++) {
            int f = tid + 256*j;
            if (WT) {
                int kk = f >> 5;
                int oq = (f & 31) << 2;
                *(float4*)(ws + kk*132 + oq) = sw[j];
            } else {
                int o = f >> 3;
                int kq = (f & 7) << 2;
                ws[(kq+0)*132 + o] = sw[j].x;
                ws[(kq+1)*132 + o] = sw[j].y;
                ws[(kq+2)*132 + o] = sw[j].z;
                ws[(kq+3)*132 + o] = sw[j].w;
            }
        }
        __syncthreads();

        // prefetch next block into regs (LDGs drain under the compute loop)
        const int kn = kb + 32;
        if (kn < k0 + kchunk) {
#pragma unroll
            for (int j = 0; j < 2; j++) {
                int f = tid + 256*j;
                int n = f >> 3;
                int kq = (f & 7) << 2;
                sa[j] = *(const float4*)(act + (size_t)(nbase+n)*K + kn + kq);
            }
#pragma unroll
            for (int j = 0; j < 4; j++) {
                int f = tid + 256*j;
                if (WT) {
                    int kk = f >> 5;
                    int oq = (f & 31) << 2;
                    sw[j] = *(const float4*)(w + (size_t)(kn+kk)*O + ocbase + oq);
                } else {
                    int o = f >> 3;
                    int kq = (f & 7) << 2;
                    sw[j] = *(const float4*)(w + (size_t)(ocbase+o)*K + kn + kq);
                }
            }
        }

        const float* tp = th + wid*8*36;
#pragma unroll 4
        for (int kk = 0; kk < 32; kk++) {
            float2 w0 = *(const float2*)(ws + kk*132 + 2*lane);
            float2 w1 = *(const float2*)(ws + kk*132 + 64 + 2*lane);
            unsigned long long wp0 = pack2(w0.x, w0.y);
            unsigned long long wp1 = pack2(w1.x, w1.y);
#pragma unroll
            for (int j = 0; j < 8; j++) {
                float t = tp[j*36 + kk];
                unsigned long long t2 = pack2(t, t);
                ffma2(acc[0][j], wp0, t2);
                ffma2(acc[1][j], wp1, t2);
            }
        }
        __syncthreads();
    }
#pragma unroll
    for (int j = 0; j < 8; j++) {
        int n = nbase + wid*8 + j;
        float* dst = part + ((size_t)sidx*Nn + n)*O + ocbase;
        *(float2*)(dst + 2*lane)      = *(float2*)&acc[0][j];
        *(float2*)(dst + 64 + 2*lane) = *(float2*)&acc[1][j];
    }
}

// ============ deterministic split-K reduce + bias, float4, S unrolled ============
template<int S>
__global__ __launch_bounds__(128) void reduce4_kernel(
    const float* __restrict__ part, float* __restrict__ dst,
    const float* __restrict__ bias, int omask, int total)
{
    int i4 = (blockIdx.x*blockDim.x + threadIdx.x) * 4;
    if (i4 >= total) return;
    float4 a = make_float4(0.f, 0.f, 0.f, 0.f);
#pragma unroll
    for (int s = 0; s < S; s++) {
        float4 p = *(const float4*)(part + (size_t)s*total + i4);
        a.x += p.x; a.y += p.y; a.z += p.z; a.w += p.w;
    }
    if (bias) {
        float4 b = *(const float4*)(bias + (i4 & omask));
        a.x += b.x; a.y += b.y; a.z += b.z; a.w += b.w;
    }
    *(float4*)(dst + i4) = a;
}

// ===================== shared attn math (attn4/attn5) =====================
// vac held as f32x2 accumulators: comp0 = sum(p.x*x.x + p.z*x.z),
// comp1 = sum(p.y*x.y + p.w*x.w); horizontal add in epilogue.
struct AttnState {
    float ur[8];
    unsigned long long vac2[8];
    float s_run;
};

__device__ __forceinline__ void attn_load_u(AttnState& st, const float* __restrict__ upart,
                                            int n, int w, int cs)
{
    st.s_run = 0.f;
#pragma unroll
    for (int i = 0; i < 8; i++) {
        float a = 0.f;
#pragma unroll
        for (int s = 0; s < 4; s++)
            a += upart[(size_t)s*Nn*C + n*C + w*128 + i*16 + cs];
        st.ur[i] = a;
        st.vac2[i] = 0ull;
    }
}

// score partial + shfl reduce (before barrier); f32x2-packed FMA
__device__ __forceinline__ float4 attn_score(const float4 (&x)[8], const AttnState& st)
{
    unsigned long long sxy = 0ull, szw = 0ull;
#pragma unroll
    for (int i = 0; i < 8; i++) {
        unsigned long long u2 = pack2(st.ur[i], st.ur[i]);
        ffma2(sxy, u2, pack2(x[i].x, x[i].y));
        ffma2(szw, u2, pack2(x[i].z, x[i].w));
    }
    float4 s4;
    unpack2(sxy, s4.x, s4.y);
    unpack2(szw, s4.z, s4.w);
#pragma unroll
    for (int off = 2; off <= 16; off <<= 1) {
        s4.x += __shfl_xor_sync(~0u, s4.x, off);
        s4.y += __shfl_xor_sync(~0u, s4.y, off);
        s4.z += __shfl_xor_sync(~0u, s4.z, off);
        s4.w += __shfl_xor_sync(~0u, s4.w, off);
    }
    return s4;
}

// cross-warp combine + softmax + vac accumulate (after barrier)
__device__ __forceinline__ void attn_finish(const float4 (&x)[8], AttnState& st,
                                            float4 (*sp)[16][2], int buf, int th)
{
    unsigned long long txy = 0ull, tzw = 0ull;
#pragma unroll
    for (int ww = 0; ww < 16; ww++) {
        const unsigned long long* q = (const unsigned long long*)&sp[buf][ww][th];
        fadd2(txy, q[0]);
        fadd2(tzw, q[1]);
    }
    float tx, ty, tz, tw;
    unpack2(txy, tx, ty);
    unpack2(tzw, tz, tw);
    const float scale = 0.044194173824159216f;  // 1/sqrt(512)
    float4 p4;
    p4.x = __expf(tx * scale);
    p4.y = __expf(ty * scale);
    p4.z = __expf(tz * scale);
    p4.w = __expf(tw * scale);
    st.s_run += (p4.x + p4.y) + (p4.z + p4.w);
    unsigned long long pxy = pack2(p4.x, p4.y);
    unsigned long long pzw = pack2(p4.z, p4.w);
#pragma unroll
    for (int i = 0; i < 8; i++) {
        ffma2(st.vac2[i], pxy, pack2(x[i].x, x[i].y));
        ffma2(st.vac2[i], pzw, pack2(x[i].z, x[i].w));
    }
}

__device__ __forceinline__ void attn_epilogue(AttnState& st, float* __restrict__ v,
                                              int n, int w, int cs, int th)
{
    float stot = st.s_run + __shfl_xor_sync(~0u, st.s_run, 1);
    float inv = 1.0f / stot;
#pragma unroll
    for (int i = 0; i < 8; i++) {
        float lo, hi;
        unpack2(st.vac2[i], lo, hi);
        float t = lo + hi;
        t += __shfl_xor_sync(~0u, t, 1);
        if (th == 0) v[n*C + w*128 + i*16 + cs] = t * inv;
    }
}

// ============ attn v5: TMA 3-stage smem pipeline, 8-t chunks ============
#define ATTN5_STAGE_FLOATS 16384           // 2048 ch * 8 t
#define ATTN5_SMEM_BYTES   (3*ATTN5_STAGE_FLOATS*4)

__device__ __forceinline__ void attn5_issue(const CUtensorMap& tmap, int ch,
                                            float* tile, unsigned long long* mbar, int n)
{
    int stg = ch - (ch/3)*3;
    unsigned mb = smem_u32(&mbar[stg]);
    asm volatile("mbarrier.arrive.expect_tx.shared.b64 _, [%0], %1;"
                 :: "r"(mb), "r"(65536u) : "memory");
    unsigned dst = smem_u32(tile + stg*ATTN5_STAGE_FLOATS);
#pragma unroll
    for (int b = 0; b < 8; b++) {
        asm volatile(
            "cp.async.bulk.tensor.2d.shared::cta.global.tile.mbarrier::complete_tx::bytes "
            "[%0], [%1, {%2, %3}], [%4];"
            :: "r"(dst + b*8192), "l"(&tmap),
               "r"(ch*8), "r"(n*C + b*256), "r"(mb)
            : "memory");
    }
}

__device__ __forceinline__ void attn5_wait(unsigned mb, int phase)
{
    asm volatile(
        "{\n\t"
        ".reg .pred P;\n"
        "W_%=:\n\t"
        "mbarrier.try_wait.parity.acquire.cta.shared::cta.b64 P, [%0], %1, 0x989680;\n\t"
        "@!P bra W_%=;\n\t"
        "}"
        :: "r"(mb), "r"(phase) : "memory");
}

__global__ __launch_bounds__(512) void attn5_kernel(
    const __grid_constant__ CUtensorMap tmap,
    const float* __restrict__ upart, float* __restrict__ v)
{
    extern __shared__ __align__(1024) float tile[];     // 3 stages
    __shared__ float4 sp[2][16][2];
    __shared__ __align__(8) unsigned long long mbar[3];

    const int n = blockIdx.x;
    const int tid = threadIdx.x;
    const int lane = tid & 31;
    const int w = tid >> 5;
    const int th = lane & 1;
    const int cs = lane >> 1;

    if (tid == 0) {
#pragma unroll
        for (int s = 0; s < 3; s++) {
            unsigned a = smem_u32(&mbar[s]);
            asm volatile("mbarrier.init.shared.b64 [%0], 1;" :: "r"(a) : "memory");
        }
    }
    __syncthreads();

    AttnState st;
    attn_load_u(st, upart, n, w, cs);

    if (tid == 0) {
        attn5_issue(tmap, 0, tile, mbar, n);
        attn5_issue(tmap, 1, tile, mbar, n);
        attn5_issue(tmap, 2, tile, mbar, n);
    }

    for (int ch = 0; ch < 64; ch++) {
        const int stg = ch - (ch/3)*3;
        attn5_wait(smem_u32(&mbar[stg]), (ch/3) & 1);

        const float* buf = tile + stg*ATTN5_STAGE_FLOATS;
        float4 x[8];
#pragma unroll
        for (int i = 0; i < 8; i++)
            x[i] = *(const float4*)(buf + (w*128 + i*16 + cs)*8 + th*4);

        float4 s4 = attn_score(x, st);
        if (lane < 2) sp[ch & 1][w][lane] = s4;
        __syncthreads();                    // also proves stage fully consumed

        if (tid == 0 && ch + 3 < 64)
            attn5_issue(tmap, ch + 3, tile, mbar, n);

        attn_finish(x, st, sp, ch & 1, th);
    }

    attn_epilogue(st, v, n, w, cs, th);
}

// ============ attn v4 (fallback if TMA encode unavailable) ============
#define ATTN_LOAD(dstbuf, chidx)                                            \
    _Pragma("unroll")                                                       \
    for (int i = 0; i < 8; i++)                                             \
        dstbuf[i] = *(const float4*)(ltn + (size_t)i*16*TT + (chidx)*8);

__global__ __launch_bounds__(512) void attn4_kernel(
    const float* __restrict__ lt, const float* __restrict__ upart,
    float* __restrict__ v)
{
    __shared__ float4 sp[2][16][2];
    const int n = blockIdx.x;
    const int tid = threadIdx.x;
    const int lane = tid & 31;
    const int w = tid >> 5;
    const int th = lane & 1;
    const int cs = lane >> 1;

    const float* ltn = lt + (size_t)n*C*TT + (size_t)(w*128 + cs)*TT + th*4;

    AttnState st;
    attn_load_u(st, upart, n, w, cs);

    float4 xa[8], xb[8];
    ATTN_LOAD(xa, 0);
    for (int ch = 0; ch < 64; ch += 2) {
        if (ch + 1 < 64) { ATTN_LOAD(xb, ch + 1); }
        {
            float4 s4 = attn_score(xa, st);
            if (lane < 2) sp[0][w][lane] = s4;
            __syncthreads();
            attn_finish(xa, st, sp, 0, th);
        }
        if (ch + 2 < 64) { ATTN_LOAD(xa, ch + 2); }
        {
            float4 s4 = attn_score(xb, st);
            if (lane < 2) sp[1][w][lane] = s4;
            __syncthreads();
            attn_finish(xb, st, sp, 1, th);
        }
    }
    attn_epilogue(st, v, n, w, cs, th);
}

// ============ fused split-K reduce (S=4) + bias + LayerNorm ============
__global__ __launch_bounds__(256) void ln2_kernel(
    const float* __restrict__ part, const float* __restrict__ bout,
    const float* __restrict__ lnw, const float* __restrict__ lnb,
    float* __restrict__ out)
{
    __shared__ float rs[8], rss[8], bc[2];
    const int n = blockIdx.x, tid = threadIdx.x;
    const int lane = tid & 31, wid = tid >> 5;
    float x[8];
    float s = 0.f, ss = 0.f;
#pragma unroll
    for (int j = 0; j < 2; j++) {
        int cbase = j*1024 + tid*4;
        float4 a = *(const float4*)(bout + cbase);
#pragma unroll
        for (int sk = 0; sk < 4; sk++) {
            float4 p = *(const float4*)(part + (size_t)sk*Nn*C + n*C + cbase);
            a.x += p.x; a.y += p.y; a.z += p.z; a.w += p.w;
        }
        x[j*4+0]=a.x; x[j*4+1]=a.y; x[j*4+2]=a.z; x[j*4+3]=a.w;
        s  += a.x + a.y + a.z + a.w;
        ss += a.x*a.x + a.y*a.y + a.z*a.z + a.w*a.w;
    }
#pragma unroll
    for (int off = 16; off; off >>= 1) {
        s  += __shfl_xor_sync(~0u, s,  off);
        ss += __shfl_xor_sync(~0u, ss, off);
    }
    if (lane == 0) { rs[wid] = s; rss[wid] = ss; }
    __syncthreads();
    if (tid == 0) {
        float S1 = 0.f, S2 = 0.f;
#pragma unroll
        for (int i = 0; i < 8; i++) { S1 += rs[i]; S2 += rss[i]; }
        float mu = S1 * (1.0f/C);
        float var = S2 * (1.0f/C) - mu*mu;
        bc[0] = mu;
        bc[1] = rsqrtf(var + 1e-5f);
    }
    __syncthreads();
    float mu = bc[0], rstd = bc[1];
#pragma unroll
    for (int j = 0; j < 2; j++) {
        int cbase = j*1024 + tid*4;
        float4 w4 = *(const float4*)(lnw + cbase);
        float4 b4 = *(const float4*)(lnb + cbase);
        float4 o;
        o.x = (x[j*4+0]-mu)*rstd*w4.x + b4.x;
        o.y = (x[j*4+1]-mu)*rstd*w4.y + b4.y;
        o.z = (x[j*4+2]-mu)*rstd*w4.z + b4.z;
        o.w = (x[j*4+3]-mu)*rstd*w4.w + b4.w;
        *(float4*)(out + (size_t)n*C + cbase) = o;
    }
}

// ===================== host =====================
typedef CUresult (*PFN_tmapEncode)(
    CUtensorMap*, CUtensorMapDataType, cuuint32_t, void*,
    const cuuint64_t*, const cuuint64_t*, const cuuint32_t*, const cuuint32_t*,
    CUtensorMapInterleave, CUtensorMapSwizzle, CUtensorMapL2promotion,
    CUtensorMapFloatOOBfill);

extern "C" void kernel_launch(void* const* d_in, const int* in_sizes, int n_in,
                              void* d_out, int out_size)
{
    const float* st_feat = (const float*)d_in[0];
    const float* lt_feat = (const float*)d_in[1];
    const float* w_st    = (const float*)d_in[2];
    const float* b_st    = (const float*)d_in[3];
    const float* w_lt    = (const float*)d_in[4];
    const float* b_lt    = (const float*)d_in[5];  (void)b_lt; // softmax-invariant
    const float* w_g     = (const float*)d_in[6];
    const float* b_g     = (const float*)d_in[7];
    const float* w_out   = (const float*)d_in[8];
    const float* b_out   = (const float*)d_in[9];
    const float* ln_w    = (const float*)d_in[10];
    const float* ln_b    = (const float*)d_in[11];
    float* out = (float*)d_out;

    float *theta, *v, *lat, *part;
    cudaGetSymbolAddress((void**)&theta, g_theta);
    cudaGetSymbolAddress((void**)&v,     g_v);
    cudaGetSymbolAddress((void**)&lat,   g_lat);
    cudaGetSymbolAddress((void**)&part,  g_part);

    // ---- TMA tensor map for lt_feat viewed as [Nn*C rows][TT cols] fp32 ----
    // L2 promotion 256B: each 32B row miss fills 256B of L2, making chunks
    // ch..ch+7 of the same channel L2-hot and giving HBM 256B-contiguous fetches.
    CUtensorMap tmap;
    bool tma_ok = false;
    {
        void* fn = nullptr;
        cudaDriverEntryPointQueryResult qr = cudaDriverEntryPointSymbolNotFound;
        if (cudaGetDriverEntryPointByVersion("cuTensorMapEncodeTiled", &fn, 12000,
                                             cudaEnableDefault, &qr) == cudaSuccess &&
            qr == cudaDriverEntryPointSuccess && fn) {
            PFN_tmapEncode enc = (PFN_tmapEncode)fn;
            cuuint64_t gdim[2] = {(cuuint64_t)TT, (cuuint64_t)Nn*C};
            cuuint64_t gstr[1] = {(cuuint64_t)TT*4};
            cuuint32_t box[2]  = {8, 256};
            cuuint32_t est[2]  = {1, 1};
            if (enc(&tmap, CU_TENSOR_MAP_DATA_TYPE_FLOAT32, 2, (void*)lt_feat,
                    gdim, gstr, box, est,
                    CU_TENSOR_MAP_INTERLEAVE_NONE, CU_TENSOR_MAP_SWIZZLE_NONE,
                    CU_TENSOR_MAP_L2_PROMOTION_L2_256B,
                    CU_TENSOR_MAP_FLOAT_OOB_FILL_NONE) == CUDA_SUCCESS)
                tma_ok = true;
        }
    }
    if (tma_ok) {
        cudaFuncSetAttribute(attn5_kernel,
            cudaFuncAttributeMaxDynamicSharedMemorySize, ATTN5_SMEM_BYTES);
    }

    // 1. theta[n,l] = st_feat @ w_st^T + b_st        [128,512]
    proj2_kernel<false><<<dim3(L/128, 2, 16), 256>>>(st_feat, w_st, part, C, L, C/16);
    reduce4_kernel<16><<<(Nn*L/4 + 127)/128, 128>>>(part, theta, b_st, L-1, Nn*L);

    // 2. u-partials[s][n][c] = theta @ w_lt chunks   (S=4; reduce fused into attn)
    proj2_kernel<true><<<dim3(C/128, 2, 4), 256>>>(theta, w_lt, part, L, C, L/4);

    // 3. v[n,c] = lt @ softmax(u.lt / sqrt(L))       [128,2048]
    if (tma_ok)
        attn5_kernel<<<Nn, 512, ATTN5_SMEM_BYTES>>>(tmap, part, v);
    else
        attn4_kernel<<<Nn, 512>>>(lt_feat, part, v);

    // 4. lat[n,l] = v @ w_g^T + b_g                  [128,512]
    proj2_kernel<false><<<dim3(L/128, 2, 16), 256>>>(v, w_g, part, C, L, C/16);
    reduce4_kernel<16><<<(Nn*L/4 + 127)/128, 128>>>(part, lat, b_g, L-1, Nn*L);

    // 5. pre-partials[s][n][c] = lat @ w_out^T chunks (S=4; reduce fused into LN)
    proj2_kernel<false><<<dim3(C/128, 2, 4), 256>>>(lat, w_out, part, L, C, L/4);

    // 6. reduce + b_out + LayerNorm -> out
    ln2_kernel<<<Nn, 256>>>(part, b_out, ln_w, ln_b, out);
}

// round 17
// speedup vs baseline: 1.0544x; 1.0544x over previous
#include <cuda_runtime.h>
#include <cuda.h>
#include <math.h>

#define Nn 128
#define C  2048
#define L  512
#define TT 512

// -------- scratch (device globals; no allocations allowed) --------
__device__ float g_theta[Nn*L];
__device__ float g_v[Nn*C];
__device__ float g_lat[Nn*L];
__device__ float g_part[16*Nn*L > 4*Nn*C ? 16*Nn*L : 4*Nn*C];  // split-K partials

// ---- helpers ----
__device__ __forceinline__ unsigned long long pack2(float a, float b) {
    unsigned long long r;
    asm("mov.b64 %0, {%1, %2};" : "=l"(r) : "r"(__float_as_uint(a)), "r"(__float_as_uint(b)));
    return r;
}
__device__ __forceinline__ void ffma2(unsigned long long& d, unsigned long long a, unsigned long long b) {
    asm("fma.rn.f32x2 %0, %1, %2, %0;" : "+l"(d) : "l"(a), "l"(b));
}
__device__ __forceinline__ unsigned smem_u32(const void* p) {
    return (unsigned)__cvta_generic_to_shared(p);
}

// ============ projection: packed-f32x2, CTA = 128 oc x 64 n, split-K ============
// Register-prefetch double buffering: block kb+1's LDGs are issued before
// computing block kb, hiding weight-DRAM latency at each barrier.
template<bool WT>
__global__ __launch_bounds__(256) void proj2_kernel(
    const float* __restrict__ act, const float* __restrict__ w,
    float* __restrict__ part, int K, int O, int kchunk)
{
    __shared__ float ws[32*132];
    __shared__ float th[64*36];
    const int tid = threadIdx.x;
    const int lane = tid & 31;
    const int wid = tid >> 5;
    const int ocbase = blockIdx.x * 128;
    const int nbase  = blockIdx.y * 64;
    const int sidx   = blockIdx.z;
    const int k0 = sidx * kchunk;

    unsigned long long acc[2][8];
#pragma unroll
    for (int p = 0; p < 2; p++)
#pragma unroll
        for (int j = 0; j < 8; j++) acc[p][j] = 0ull;

    float4 sa[2], sw[4];

    // prologue: load block k0 into regs
#pragma unroll
    for (int j = 0; j < 2; j++) {
        int f = tid + 256*j;
        int n = f >> 3;
        int kq = (f & 7) << 2;
        sa[j] = *(const float4*)(act + (size_t)(nbase+n)*K + k0 + kq);
    }
#pragma unroll
    for (int j = 0; j < 4; j++) {
        int f = tid + 256*j;
        if (WT) {
            int kk = f >> 5;
            int oq = (f & 31) << 2;
            sw[j] = *(const float4*)(w + (size_t)(k0+kk)*O + ocbase + oq);
        } else {
            int o = f >> 3;
            int kq = (f & 7) << 2;
            sw[j] = *(const float4*)(w + (size_t)(ocbase+o)*K + k0 + kq);
        }
    }

    for (int kb = k0; kb < k0 + kchunk; kb += 32) {
        // store staged regs to smem
#pragma unroll
        for (int j = 0; j < 2; j++) {
            int f = tid + 256*j;
            int n = f >> 3;
            int kq = (f & 7) << 2;
            *(float4*)(th + n*36 + kq) = sa[j];
        }
#pragma unroll
        for (int j = 0; j < 4; j++) {
            int f = tid + 256*j;
            if (WT) {
                int kk = f >> 5;
                int oq = (f & 31) << 2;
                *(float4*)(ws + kk*132 + oq) = sw[j];
            } else {
                int o = f >> 3;
                int kq = (f & 7) << 2;
                ws[(kq+0)*132 + o] = sw[j].x;
                ws[(kq+1)*132 + o] = sw[j].y;
                ws[(kq+2)*132 + o] = sw[j].z;
                ws[(kq+3)*132 + o] = sw[j].w;
            }
        }
        __syncthreads();

        // prefetch next block into regs (LDGs drain under the compute loop)
        const int kn = kb + 32;
        if (kn < k0 + kchunk) {
#pragma unroll
            for (int j = 0; j < 2; j++) {
                int f = tid + 256*j;
                int n = f >> 3;
                int kq = (f & 7) << 2;
                sa[j] = *(const float4*)(act + (size_t)(nbase+n)*K + kn + kq);
            }
#pragma unroll
            for (int j = 0; j < 4; j++) {
                int f = tid + 256*j;
                if (WT) {
                    int kk = f >> 5;
                    int oq = (f & 31) << 2;
                    sw[j] = *(const float4*)(w + (size_t)(kn+kk)*O + ocbase + oq);
                } else {
                    int o = f >> 3;
                    int kq = (f & 7) << 2;
                    sw[j] = *(const float4*)(w + (size_t)(ocbase+o)*K + kn + kq);
                }
            }
        }

        const float* tp = th + wid*8*36;
#pragma unroll 4
        for (int kk = 0; kk < 32; kk++) {
            float2 w0 = *(const float2*)(ws + kk*132 + 2*lane);
            float2 w1 = *(const float2*)(ws + kk*132 + 64 + 2*lane);
            unsigned long long wp0 = pack2(w0.x, w0.y);
            unsigned long long wp1 = pack2(w1.x, w1.y);
#pragma unroll
            for (int j = 0; j < 8; j++) {
                float t = tp[j*36 + kk];
                unsigned long long t2 = pack2(t, t);
                ffma2(acc[0][j], wp0, t2);
                ffma2(acc[1][j], wp1, t2);
            }
        }
        __syncthreads();
    }
#pragma unroll
    for (int j = 0; j < 8; j++) {
        int n = nbase + wid*8 + j;
        float* dst = part + ((size_t)sidx*Nn + n)*O + ocbase;
        *(float2*)(dst + 2*lane)      = *(float2*)&acc[0][j];
        *(float2*)(dst + 64 + 2*lane) = *(float2*)&acc[1][j];
    }
}

// ============ deterministic split-K reduce + bias, float4, S unrolled ============
template<int S>
__global__ __launch_bounds__(128) void reduce4_kernel(
    const float* __restrict__ part, float* __restrict__ dst,
    const float* __restrict__ bias, int omask, int total)
{
    int i4 = (blockIdx.x*blockDim.x + threadIdx.x) * 4;
    if (i4 >= total) return;
    float4 a = make_float4(0.f, 0.f, 0.f, 0.f);
#pragma unroll
    for (int s = 0; s < S; s++) {
        float4 p = *(const float4*)(part + (size_t)s*total + i4);
        a.x += p.x; a.y += p.y; a.z += p.z; a.w += p.w;
    }
    if (bias) {
        float4 b = *(const float4*)(bias + (i4 & omask));
        a.x += b.x; a.y += b.y; a.z += b.z; a.w += b.w;
    }
    *(float4*)(dst + i4) = a;
}

// ===================== shared attn math (attn4/attn5) =====================
struct AttnState {
    float ur[8];
    float vac[8];
    float s_run;
};

__device__ __forceinline__ void attn_load_u(AttnState& st, const float* __restrict__ upart,
                                            int n, int w, int cs)
{
    st.s_run = 0.f;
#pragma unroll
    for (int i = 0; i < 8; i++) {
        float a = 0.f;
#pragma unroll
        for (int s = 0; s < 4; s++)
            a += upart[(size_t)s*Nn*C + n*C + w*128 + i*16 + cs];
        st.ur[i] = a;
        st.vac[i] = 0.f;
    }
}

// score partial + shfl reduce (before barrier)
__device__ __forceinline__ float4 attn_score(const float4 (&x)[8], const AttnState& st)
{
    float4 s4 = make_float4(0.f, 0.f, 0.f, 0.f);
#pragma unroll
    for (int i = 0; i < 8; i++) {
        s4.x += st.ur[i]*x[i].x; s4.y += st.ur[i]*x[i].y;
        s4.z += st.ur[i]*x[i].z; s4.w += st.ur[i]*x[i].w;
    }
#pragma unroll
    for (int off = 2; off <= 16; off <<= 1) {
        s4.x += __shfl_xor_sync(~0u, s4.x, off);
        s4.y += __shfl_xor_sync(~0u, s4.y, off);
        s4.z += __shfl_xor_sync(~0u, s4.z, off);
        s4.w += __shfl_xor_sync(~0u, s4.w, off);
    }
    return s4;
}

// cross-warp combine + softmax + vac accumulate (after barrier)
__device__ __forceinline__ void attn_finish(const float4 (&x)[8], AttnState& st,
                                            float4 (*sp)[16][2], int buf, int th)
{
    float4 tot = make_float4(0.f, 0.f, 0.f, 0.f);
#pragma unroll
    for (int ww = 0; ww < 16; ww++) {
        float4 q = sp[buf][ww][th];
        tot.x += q.x; tot.y += q.y; tot.z += q.z; tot.w += q.w;
    }
    const float scale = 0.044194173824159216f;  // 1/sqrt(512)
    float4 p4;
    p4.x = __expf(tot.x * scale);
    p4.y = __expf(tot.y * scale);
    p4.z = __expf(tot.z * scale);
    p4.w = __expf(tot.w * scale);
    st.s_run += (p4.x + p4.y) + (p4.z + p4.w);
#pragma unroll
    for (int i = 0; i < 8; i++) {
        float a = st.vac[i];
        a += p4.x*x[i].x; a += p4.y*x[i].y;
        a += p4.z*x[i].z; a += p4.w*x[i].w;
        st.vac[i] = a;
    }
}

__device__ __forceinline__ void attn_epilogue(AttnState& st, float* __restrict__ v,
                                              int n, int w, int cs, int th)
{
    float stot = st.s_run + __shfl_xor_sync(~0u, st.s_run, 1);
    float inv = 1.0f / stot;
#pragma unroll
    for (int i = 0; i < 8; i++) {
        float t = st.vac[i] + __shfl_xor_sync(~0u, st.vac[i], 1);
        if (th == 0) v[n*C + w*128 + i*16 + cs] = t * inv;
    }
}

// ============ attn v5: TMA 3-stage smem pipeline, 8-t chunks (best: 91.3us) ============
#define ATTN5_STAGE_FLOATS 16384           // 2048 ch * 8 t
#define ATTN5_SMEM_BYTES   (3*ATTN5_STAGE_FLOATS*4)

__device__ __forceinline__ void attn5_issue(const CUtensorMap& tmap, int ch,
                                            float* tile, unsigned long long* mbar, int n)
{
    int stg = ch - (ch/3)*3;
    unsigned mb = smem_u32(&mbar[stg]);
    asm volatile("mbarrier.arrive.expect_tx.shared.b64 _, [%0], %1;"
                 :: "r"(mb), "r"(65536u) : "memory");
    unsigned dst = smem_u32(tile + stg*ATTN5_STAGE_FLOATS);
#pragma unroll
    for (int b = 0; b < 8; b++) {
        asm volatile(
            "cp.async.bulk.tensor.2d.shared::cta.global.tile.mbarrier::complete_tx::bytes "
            "[%0], [%1, {%2, %3}], [%4];"
            :: "r"(dst + b*8192), "l"(&tmap),
               "r"(ch*8), "r"(n*C + b*256), "r"(mb)
            : "memory");
    }
}

__device__ __forceinline__ void attn5_wait(unsigned mb, int phase)
{
    asm volatile(
        "{\n\t"
        ".reg .pred P;\n"
        "W_%=:\n\t"
        "mbarrier.try_wait.parity.acquire.cta.shared::cta.b64 P, [%0], %1, 0x989680;\n\t"
        "@!P bra W_%=;\n\t"
        "}"
        :: "r"(mb), "r"(phase) : "memory");
}

__global__ __launch_bounds__(512) void attn5_kernel(
    const __grid_constant__ CUtensorMap tmap,
    const float* __restrict__ upart, float* __restrict__ v)
{
    extern __shared__ __align__(1024) float tile[];     // 3 stages
    __shared__ float4 sp[2][16][2];
    __shared__ __align__(8) unsigned long long mbar[3];

    const int n = blockIdx.x;
    const int tid = threadIdx.x;
    const int lane = tid & 31;
    const int w = tid >> 5;
    const int th = lane & 1;
    const int cs = lane >> 1;

    if (tid == 0) {
#pragma unroll
        for (int s = 0; s < 3; s++) {
            unsigned a = smem_u32(&mbar[s]);
            asm volatile("mbarrier.init.shared.b64 [%0], 1;" :: "r"(a) : "memory");
        }
    }
    __syncthreads();

    AttnState st;
    attn_load_u(st, upart, n, w, cs);

    if (tid == 0) {
        attn5_issue(tmap, 0, tile, mbar, n);
        attn5_issue(tmap, 1, tile, mbar, n);
        attn5_issue(tmap, 2, tile, mbar, n);
    }

    for (int ch = 0; ch < 64; ch++) {
        const int stg = ch - (ch/3)*3;
        attn5_wait(smem_u32(&mbar[stg]), (ch/3) & 1);

        const float* buf = tile + stg*ATTN5_STAGE_FLOATS;
        float4 x[8];
#pragma unroll
        for (int i = 0; i < 8; i++)
            x[i] = *(const float4*)(buf + (w*128 + i*16 + cs)*8 + th*4);

        float4 s4 = attn_score(x, st);
        if (lane < 2) sp[ch & 1][w][lane] = s4;
        __syncthreads();                    // also proves stage fully consumed

        if (tid == 0 && ch + 3 < 64)
            attn5_issue(tmap, ch + 3, tile, mbar, n);

        attn_finish(x, st, sp, ch & 1, th);
    }

    attn_epilogue(st, v, n, w, cs, th);
}

// ============ attn v4 (fallback if TMA encode unavailable) ============
#define ATTN_LOAD(dstbuf, chidx)                                            \
    _Pragma("unroll")                                                       \
    for (int i = 0; i < 8; i++)                                             \
        dstbuf[i] = *(const float4*)(ltn + (size_t)i*16*TT + (chidx)*8);

__global__ __launch_bounds__(512) void attn4_kernel(
    const float* __restrict__ lt, const float* __restrict__ upart,
    float* __restrict__ v)
{
    __shared__ float4 sp[2][16][2];
    const int n = blockIdx.x;
    const int tid = threadIdx.x;
    const int lane = tid & 31;
    const int w = tid >> 5;
    const int th = lane & 1;
    const int cs = lane >> 1;

    const float* ltn = lt + (size_t)n*C*TT + (size_t)(w*128 + cs)*TT + th*4;

    AttnState st;
    attn_load_u(st, upart, n, w, cs);

    float4 xa[8], xb[8];
    ATTN_LOAD(xa, 0);
    for (int ch = 0; ch < 64; ch += 2) {
        if (ch + 1 < 64) { ATTN_LOAD(xb, ch + 1); }
        {
            float4 s4 = attn_score(xa, st);
            if (lane < 2) sp[0][w][lane] = s4;
            __syncthreads();
            attn_finish(xa, st, sp, 0, th);
        }
        if (ch + 2 < 64) { ATTN_LOAD(xa, ch + 2); }
        {
            float4 s4 = attn_score(xb, st);
            if (lane < 2) sp[1][w][lane] = s4;
            __syncthreads();
            attn_finish(xb, st, sp, 1, th);
        }
    }
    attn_epilogue(st, v, n, w, cs, th);
}

// ============ fused split-K reduce (S=4) + bias + LayerNorm ============
__global__ __launch_bounds__(256) void ln2_kernel(
    const float* __restrict__ part, const float* __restrict__ bout,
    const float* __restrict__ lnw, const float* __restrict__ lnb,
    float* __restrict__ out)
{
    __shared__ float rs[8], rss[8], bc[2];
    const int n = blockIdx.x, tid = threadIdx.x;
    const int lane = tid & 31, wid = tid >> 5;
    float x[8];
    float s = 0.f, ss = 0.f;
#pragma unroll
    for (int j = 0; j < 2; j++) {
        int cbase = j*1024 + tid*4;
        float4 a = *(const float4*)(bout + cbase);
#pragma unroll
        for (int sk = 0; sk < 4; sk++) {
            float4 p = *(const float4*)(part + (size_t)sk*Nn*C + n*C + cbase);
            a.x += p.x; a.y += p.y; a.z += p.z; a.w += p.w;
        }
        x[j*4+0]=a.x; x[j*4+1]=a.y; x[j*4+2]=a.z; x[j*4+3]=a.w;
        s  += a.x + a.y + a.z + a.w;
        ss += a.x*a.x + a.y*a.y + a.z*a.z + a.w*a.w;
    }
#pragma unroll
    for (int off = 16; off; off >>= 1) {
        s  += __shfl_xor_sync(~0u, s,  off);
        ss += __shfl_xor_sync(~0u, ss, off);
    }
    if (lane == 0) { rs[wid] = s; rss[wid] = ss; }
    __syncthreads();
    if (tid == 0) {
        float S1 = 0.f, S2 = 0.f;
#pragma unroll
        for (int i = 0; i < 8; i++) { S1 += rs[i]; S2 += rss[i]; }
        float mu = S1 * (1.0f/C);
        float var = S2 * (1.0f/C) - mu*mu;
        bc[0] = mu;
        bc[1] = rsqrtf(var + 1e-5f);
    }
    __syncthreads();
    float mu = bc[0], rstd = bc[1];
#pragma unroll
    for (int j = 0; j < 2; j++) {
        int cbase = j*1024 + tid*4;
        float4 w4 = *(const float4*)(lnw + cbase);
        float4 b4 = *(const float4*)(lnb + cbase);
        float4 o;
        o.x = (x[j*4+0]-mu)*rstd*w4.x + b4.x;
        o.y = (x[j*4+1]-mu)*rstd*w4.y + b4.y;
        o.z = (x[j*4+2]-mu)*rstd*w4.z + b4.z;
        o.w = (x[j*4+3]-mu)*rstd*w4.w + b4.w;
        *(float4*)(out + (size_t)n*C + cbase) = o;
    }
}

// ===================== host =====================
typedef CUresult (*PFN_tmapEncode)(
    CUtensorMap*, CUtensorMapDataType, cuuint32_t, void*,
    const cuuint64_t*, const cuuint64_t*, const cuuint32_t*, const cuuint32_t*,
    CUtensorMapInterleave, CUtensorMapSwizzle, CUtensorMapL2promotion,
    CUtensorMapFloatOOBfill);

extern "C" void kernel_launch(void* const* d_in, const int* in_sizes, int n_in,
                              void* d_out, int out_size)
{
    const float* st_feat = (const float*)d_in[0];
    const float* lt_feat = (const float*)d_in[1];
    const float* w_st    = (const float*)d_in[2];
    const float* b_st    = (const float*)d_in[3];
    const float* w_lt    = (const float*)d_in[4];
    const float* b_lt    = (const float*)d_in[5];  (void)b_lt; // softmax-invariant
    const float* w_g     = (const float*)d_in[6];
    const float* b_g     = (const float*)d_in[7];
    const float* w_out   = (const float*)d_in[8];
    const float* b_out   = (const float*)d_in[9];
    const float* ln_w    = (const float*)d_in[10];
    const float* ln_b    = (const float*)d_in[11];
    float* out = (float*)d_out;

    float *theta, *v, *lat, *part;
    cudaGetSymbolAddress((void**)&theta, g_theta);
    cudaGetSymbolAddress((void**)&v,     g_v);
    cudaGetSymbolAddress((void**)&lat,   g_lat);
    cudaGetSymbolAddress((void**)&part,  g_part);

    // ---- TMA tensor map for lt_feat viewed as [Nn*C rows][TT cols] fp32 ----
    CUtensorMap tmap;
    bool tma_ok = false;
    {
        void* fn = nullptr;
        cudaDriverEntryPointQueryResult qr = cudaDriverEntryPointSymbolNotFound;
        if (cudaGetDriverEntryPointByVersion("cuTensorMapEncodeTiled", &fn, 12000,
                                             cudaEnableDefault, &qr) == cudaSuccess &&
            qr == cudaDriverEntryPointSuccess && fn) {
            PFN_tmapEncode enc = (PFN_tmapEncode)fn;
            cuuint64_t gdim[2] = {(cuuint64_t)TT, (cuuint64_t)Nn*C};
            cuuint64_t gstr[1] = {(cuuint64_t)TT*4};
            cuuint32_t box[2]  = {8, 256};
            cuuint32_t est[2]  = {1, 1};
            if (enc(&tmap, CU_TENSOR_MAP_DATA_TYPE_FLOAT32, 2, (void*)lt_feat,
                    gdim, gstr, box, est,
                    CU_TENSOR_MAP_INTERLEAVE_NONE, CU_TENSOR_MAP_SWIZZLE_NONE,
                    CU_TENSOR_MAP_L2_PROMOTION_L2_128B,
                    CU_TENSOR_MAP_FLOAT_OOB_FILL_NONE) == CUDA_SUCCESS)
                tma_ok = true;
        }
    }
    if (tma_ok) {
        cudaFuncSetAttribute(attn5_kernel,
            cudaFuncAttributeMaxDynamicSharedMemorySize, ATTN5_SMEM_BYTES);
    }

    // 1. theta[n,l] = st_feat @ w_st^T + b_st        [128,512]
    proj2_kernel<false><<<dim3(L/128, 2, 16), 256>>>(st_feat, w_st, part, C, L, C/16);
    reduce4_kernel<16><<<(Nn*L/4 + 127)/128, 128>>>(part, theta, b_st, L-1, Nn*L);

    // 2. u-partials[s][n][c] = theta @ w_lt chunks   (S=4; reduce fused into attn)
    proj2_kernel<true><<<dim3(C/128, 2, 4), 256>>>(theta, w_lt, part, L, C, L/4);

    // 3. v[n,c] = lt @ softmax(u.lt / sqrt(L))       [128,2048]
    if (tma_ok)
        attn5_kernel<<<Nn, 512, ATTN5_SMEM_BYTES>>>(tmap, part, v);
    else
        attn4_kernel<<<Nn, 512>>>(lt_feat, part, v);

    // 4. lat[n,l] = v @ w_g^T + b_g                  [128,512]
    proj2_kernel<false><<<dim3(L/128, 2, 16), 256>>>(v, w_g, part, C, L, C/16);
    reduce4_kernel<16><<<(Nn*L/4 + 127)/128, 128>>>(part, lat, b_g, L-1, Nn*L);

    // 5. pre-partials[s][n][c] = lat @ w_out^T chunks (S=4; reduce fused into LN)
    proj2_kernel<false><<<dim3(C/128, 2, 4), 256>>>(lat, w_out, part, L, C, L/4);

    // 6. reduce + b_out + LayerNorm -> out
    ln2_kernel<<<Nn, 256>>>(part, b_out, ln_w, ln_b, out);
}